// round 10
// baseline (speedup 1.0000x reference)
#include <cuda_runtime.h>
#include <cuda_fp16.h>
#include <math.h>
#include <stdint.h>

#define BATCH 512
#define P 1152
#define NCAPS 10
#define T 16
#define D 8
#define PD 9216          // P*D
#define NT 160           // NCAPS*T
#define KCH1 36          // split-K chunks gemm1 (36*256 = 9216)
#define NBLK 288         // persistent grid: 8*36 = 144*2 = 288, 2 CTAs/SM

// SMEM stage: K=32 halves (64B/row), 80B row stride.
#define SROW 80
#define B_OFF   5120             // 64*80
#define STAGE_BYTES 17920        // + 160*80
#define NSTAGE 4
#define SMEM_BYTES (NSTAGE*STAGE_BYTES)   // 71680 -> 2 CTAs/SM

// ---------------- scratch ----------------------------------------------------
__device__ float  g_Wt2[PD*NT];       // W [pd][nt] fp32 (gemm2 epilogue)
__device__ __half g_Xq[BATCH*PD];     // fl16(X) [b][pd]
__device__ __half g_Xtq[PD*BATCH];    // fl16(X)^T [pd][b]
__device__ __half g_Bq[NT*PD];        // fl16(c.W) [nt][pd]
__device__ __half g_vq[NT*BATCH];     // fl16(v) [nt][b]
__device__ float  g_spart[KCH1*BATCH*NT];
__device__ float  g_bbar[P*NCAPS];
__device__ float  g_b[P*NCAPS];

// global barrier state (self-resetting: even #barriers per launch)
__device__ int          g_cnt = 0;
__device__ volatile int g_sense = 0;

// ---------------- PTX helpers ------------------------------------------------
__device__ __forceinline__ void mma16816(float* c,
    uint32_t a0, uint32_t a1, uint32_t a2, uint32_t a3,
    uint32_t b0, uint32_t b1) {
    asm volatile(
        "mma.sync.aligned.m16n8k16.row.col.f32.f16.f16.f32 "
        "{%0,%1,%2,%3}, {%4,%5,%6,%7}, {%8,%9}, {%0,%1,%2,%3};"
        : "+f"(c[0]), "+f"(c[1]), "+f"(c[2]), "+f"(c[3])
        : "r"(a0), "r"(a1), "r"(a2), "r"(a3), "r"(b0), "r"(b1));
}
__device__ __forceinline__ void ldmx4(uint32_t* r, uint32_t addr) {
    asm volatile("ldmatrix.sync.aligned.m8n8.x4.shared.b16 {%0,%1,%2,%3}, [%4];"
        : "=r"(r[0]), "=r"(r[1]), "=r"(r[2]), "=r"(r[3]) : "r"(addr));
}
__device__ __forceinline__ void ldmx2(uint32_t* r, uint32_t addr) {
    asm volatile("ldmatrix.sync.aligned.m8n8.x2.shared.b16 {%0,%1}, [%2];"
        : "=r"(r[0]), "=r"(r[1]) : "r"(addr));
}
__device__ __forceinline__ uint32_t s2u(const void* p) {
    uint32_t a;
    asm("{ .reg .u64 t; cvta.to.shared.u64 t, %1; cvt.u32.u64 %0, t; }"
        : "=r"(a) : "l"(p));
    return a;
}
__device__ __forceinline__ void cpasync16(uint32_t dst, const void* src) {
    asm volatile("cp.async.cg.shared.global [%0], [%1], 16;"
        :: "r"(dst), "l"(__cvta_generic_to_global(src)));
}
#define CP_COMMIT() asm volatile("cp.async.commit_group;" ::: "memory")
#define CP_WAIT(n)  asm volatile("cp.async.wait_group %0;" :: "n"(n) : "memory")

// ---------------- global barrier (sense-reversing, k = 1..10) ----------------
__device__ __forceinline__ void gbar(int k) {
    __threadfence();
    __syncthreads();
    if (threadIdx.x == 0) {
        int t = atomicAdd(&g_cnt, 1);
        if (t == NBLK - 1) {
            g_cnt = 0;
            __threadfence();
            g_sense = k & 1;
        } else {
            while (g_sense != (k & 1)) __nanosleep(64);
        }
    }
    __syncthreads();
}

// ---------------- compute one K=32 stage -------------------------------------
// 8 warps as 2(M) x 4(N); warp tile 32(M) x 40(N); pure fp16 operands
__device__ __forceinline__ void compute_stage(
    uint32_t base, int wm32, int wn40, int lane, float acc[2][5][4]) {
    int grp = lane >> 3, lr = lane & 7;
    #pragma unroll
    for (int ko = 0; ko < 32; ko += 16) {
        uint32_t bh[5][2];
        #pragma unroll
        for (int bp = 0; bp < 2; ++bp) {
            uint32_t ba = (uint32_t)((wn40 + bp*16 + ((grp & 2) << 2) + lr)*SROW
                                     + (ko + (grp & 1)*8)*2);
            uint32_t r4[4];
            ldmx4(r4, base + B_OFF + ba);
            bh[bp*2][0]   = r4[0]; bh[bp*2][1]   = r4[1];
            bh[bp*2+1][0] = r4[2]; bh[bp*2+1][1] = r4[3];
        }
        {
            uint32_t ba = (uint32_t)((wn40 + 32 + lr)*SROW + (ko + (grp & 1)*8)*2);
            ldmx2(bh[4], base + B_OFF + ba);
        }
        #pragma unroll
        for (int mt = 0; mt < 2; ++mt) {
            uint32_t aa = (uint32_t)((wm32 + mt*16 + (grp & 1)*8 + lr)*SROW
                                     + (ko + (grp >> 1)*8)*2);
            uint32_t ah[4];
            ldmx4(ah, base + aa);
            #pragma unroll
            for (int bt = 0; bt < 5; ++bt)
                mma16816(acc[mt][bt], ah[0], ah[1], ah[2], ah[3], bh[bt][0], bh[bt][1]);
        }
    }
}

// ---------------- persistent mega-kernel -------------------------------------
__global__ void __launch_bounds__(256, 2) k_mega(
    const float* __restrict__ W, const float* __restrict__ X,
    float* __restrict__ out) {
    extern __shared__ char smem[];
    uint32_t sb = s2u(smem);
    const int bid = blockIdx.x;
    const int tid = threadIdx.x;
    const int wid = tid >> 5, lane = tid & 31;
    const int wm32 = (wid >> 2) * 32;
    const int wn40 = (wid & 3) * 40;
    const int g = lane >> 2, qq = (lane & 3)*2;

    // ================= PHASE 0: prep =========================================
    // W-part: 5760 virtual blocks of 256 elems (NT*PD)
    for (int vb = bid; vb < 5760; vb += NBLK) {
        int i = vb * 256 + tid;
        int nt = i / PD, pd = i - nt*PD;
        int p = pd >> 3, d = pd & 7, n = nt >> 4, t = nt & 15;
        float w = W[((p*NCAPS + n)*T + t)*D + d];
        g_Wt2[(size_t)pd*NT + nt] = w;
        g_Bq[i] = __float2half_rn(0.1f * w);   // iter-0 coupling c = 1/NCAPS
        if (i < P*NCAPS) g_b[i] = 0.0f;
    }
    // X-part: 4608 virtual blocks (PD/32=288 x BATCH/32=16)
    {
        __half (*tb)[33] = (__half(*)[33])smem;
        int tx = tid & 31, ty = tid >> 5;
        for (int vb = bid; vb < 4608; vb += NBLK) {
            int pd0 = (vb % 288) * 32, b0 = (vb / 288) * 32;
            #pragma unroll
            for (int j = 0; j < 32; j += 8) {
                float v = X[(size_t)(b0 + ty + j)*PD + pd0 + tx];
                __half h = __float2half_rn(v);
                g_Xq[(size_t)(b0 + ty + j)*PD + pd0 + tx] = h;
                tb[ty + j][tx] = h;
            }
            __syncthreads();
            #pragma unroll
            for (int j = 0; j < 32; j += 8)
                g_Xtq[(size_t)(pd0 + ty + j)*BATCH + b0 + tx] = tb[tx][ty + j];
            __syncthreads();
        }
    }
    gbar(1);

    #pragma unroll 1
    for (int it = 0; it < 3; ++it) {
        // ============== GEMM1: spart[by] = X[64b x 256k] * Bq[256k x 160] ====
        {
            int b0 = (bid & 7) * 64;
            int kc = (bid >> 3) * 256;

            float acc[2][5][4];
            #pragma unroll
            for (int i = 0; i < 2; ++i)
                #pragma unroll
                for (int j = 0; j < 5; ++j)
                    #pragma unroll
                    for (int r = 0; r < 4; ++r) acc[i][j][r] = 0.0f;

            auto issue = [&](int s, int buf) {
                int kb = kc + s*32;
                uint32_t base = sb + buf*STAGE_BYTES;
                {
                    int row = tid >> 2, q = tid & 3;
                    cpasync16(base + row*SROW + q*16,
                              g_Xq + (size_t)(b0 + row)*PD + kb + q*8);
                }
                #pragma unroll
                for (int u = 0; u < 3; ++u) {
                    int ch = tid + 256*u;
                    if (ch < 640) {
                        int row = ch >> 2, q = ch & 3;
                        cpasync16(base + B_OFF + row*SROW + q*16,
                                  g_Bq + (size_t)row*PD + kb + q*8);
                    }
                }
            };

            issue(0, 0); CP_COMMIT();
            issue(1, 1); CP_COMMIT();
            issue(2, 2); CP_COMMIT();
            #pragma unroll 1
            for (int s = 0; s < 8; ++s) {
                CP_WAIT(2);
                __syncthreads();
                if (s + 3 < 8) issue(s + 3, (s + 3) & 3);
                CP_COMMIT();
                compute_stage(sb + (s & 3)*STAGE_BYTES, wm32, wn40, lane, acc);
            }

            float* o = g_spart + (size_t)(bid >> 3) * BATCH * NT;
            #pragma unroll
            for (int mt = 0; mt < 2; ++mt) {
                int row = b0 + wm32 + mt*16 + g;
                #pragma unroll
                for (int bt = 0; bt < 5; ++bt) {
                    int col = wn40 + bt*8 + qq;
                    *(float2*)&o[(size_t)row*NT + col]       = make_float2(acc[mt][bt][0], acc[mt][bt][1]);
                    *(float2*)&o[(size_t)(row + 8)*NT + col] = make_float2(acc[mt][bt][2], acc[mt][bt][3]);
                }
            }
        }
        gbar(2 + it*4);

        // ============== redsquash (80 blocks active) =========================
        {
            int i4 = bid * 256 + tid;
            if (i4 < BATCH*NT/4) {
                const float4* sp = (const float4*)g_spart;
                float4 s = make_float4(0.0f, 0.0f, 0.0f, 0.0f);
                #pragma unroll
                for (int ch = 0; ch < KCH1; ++ch) {
                    float4 t = __ldcg(&sp[(size_t)ch*(BATCH*NT/4) + i4]);
                    s.x += t.x; s.y += t.y; s.z += t.z; s.w += t.w;
                }
                float ss = s.x*s.x + s.y*s.y + s.z*s.z + s.w*s.w;
                #pragma unroll
                for (int o2 = 1; o2 < 4; o2 <<= 1)
                    ss += __shfl_xor_sync(0xffffffffu, ss, o2);
                float nrm = sqrtf(ss);
                float f = ss / (1.0f + ss*(nrm + 1e-9f));
                float4 v = make_float4(f*s.x, f*s.y, f*s.z, f*s.w);
                if (it == 2) {
                    ((float4*)out)[i4] = v;
                } else {
                    int idx = 4*i4;
                    int b = idx / NT, nt = idx - b*NT;
                    g_vq[(size_t)nt*BATCH + b]     = __float2half_rn(v.x);
                    g_vq[(size_t)(nt+1)*BATCH + b] = __float2half_rn(v.y);
                    g_vq[(size_t)(nt+2)*BATCH + b] = __float2half_rn(v.z);
                    g_vq[(size_t)(nt+3)*BATCH + b] = __float2half_rn(v.w);
                    if (i4 < P*NCAPS/4)
                        ((float4*)g_bbar)[i4] = make_float4(0.0f, 0.0f, 0.0f, 0.0f);
                }
            }
        }
        if (it == 2) break;            // final output written; kernel done
        gbar(3 + it*4);

        // ============== GEMM2 + fused agreement ==============================
        {
            __shared__ float bb[8][12];
            int pd0 = (bid % 144) * 64;
            int kc = (bid / 144) * 256;

            if (tid < 80) bb[tid / 10][tid % 10] = 0.0f;

            float acc[2][5][4];
            #pragma unroll
            for (int i = 0; i < 2; ++i)
                #pragma unroll
                for (int j = 0; j < 5; ++j)
                    #pragma unroll
                    for (int r = 0; r < 4; ++r) acc[i][j][r] = 0.0f;

            auto issue = [&](int s, int buf) {
                int kb = kc + s*32;
                uint32_t base = sb + buf*STAGE_BYTES;
                {
                    int row = tid >> 2, q = tid & 3;
                    cpasync16(base + row*SROW + q*16,
                              g_Xtq + (size_t)(pd0 + row)*BATCH + kb + q*8);
                }
                #pragma unroll
                for (int u = 0; u < 3; ++u) {
                    int ch = tid + 256*u;
                    if (ch < 640) {
                        int row = ch >> 2, q = ch & 3;
                        cpasync16(base + B_OFF + row*SROW + q*16,
                                  g_vq + (size_t)row*BATCH + kb + q*8);
                    }
                }
            };

            issue(0, 0); CP_COMMIT();
            issue(1, 1); CP_COMMIT();
            issue(2, 2); CP_COMMIT();
            #pragma unroll 1
            for (int s = 0; s < 8; ++s) {
                CP_WAIT(2);
                __syncthreads();
                if (s + 3 < 8) issue(s + 3, (s + 3) & 3);
                CP_COMMIT();
                compute_stage(sb + (s & 3)*STAGE_BYTES, wm32, wn40, lane, acc);
            }

            // fused agreement epilogue
            #pragma unroll
            for (int mt = 0; mt < 2; ++mt) {
                int r0 = wm32 + mt*16 + g;
                int p0 = (wm32 + mt*16) >> 3;
                #pragma unroll
                for (int bt = 0; bt < 5; ++bt) {
                    int col = wn40 + bt*8 + qq;
                    int n = col >> 4;
                    float2 w0 = *(const float2*)&g_Wt2[(size_t)(pd0 + r0)*NT + col];
                    float2 w1 = *(const float2*)&g_Wt2[(size_t)(pd0 + r0 + 8)*NT + col];
                    float v0 = acc[mt][bt][0]*w0.x + acc[mt][bt][1]*w0.y;
                    float v1 = acc[mt][bt][2]*w1.x + acc[mt][bt][3]*w1.y;
                    #pragma unroll
                    for (int o2 = 4; o2 < 32; o2 <<= 1) {
                        v0 += __shfl_xor_sync(0xffffffffu, v0, o2);
                        v1 += __shfl_xor_sync(0xffffffffu, v1, o2);
                    }
                    if (lane < 4) {
                        atomicAdd(&bb[p0][n], v0);
                        atomicAdd(&bb[p0 + 1][n], v1);
                    }
                }
            }
            __syncthreads();
            if (tid < 80) {
                const float inv = 1.0f / (float)BATCH;
                atomicAdd(&g_bbar[(pd0/8 + tid/10)*NCAPS + tid % 10],
                          bb[tid / 10][tid % 10] * inv);
            }
        }
        gbar(4 + it*4);

        // ============== route + B quantize (144 blocks active) ===============
        if (bid < 144) {
            __shared__ float sbn[8][10];
            __shared__ float sc[8][10];
            int p0 = bid * 8;
            int pd0 = bid * 64;

            if (tid < 80) {
                int lp = tid / 10, n = tid - lp*10;
                int p = p0 + lp;
                float bn = g_b[p*NCAPS + n] + __ldcg(&g_bbar[p*NCAPS + n]);
                g_b[p*NCAPS + n] = bn;
                sbn[lp][n] = bn;
            }
            __syncthreads();
            if (tid < 8) {
                float mx = -1e30f;
                #pragma unroll
                for (int n = 0; n < NCAPS; ++n) mx = fmaxf(mx, sbn[tid][n]);
                float sum = 0.0f;
                float e[NCAPS];
                #pragma unroll
                for (int n = 0; n < NCAPS; ++n) { e[n] = expf(sbn[tid][n] - mx); sum += e[n]; }
                float rs = 1.0f / sum;
                #pragma unroll
                for (int n = 0; n < NCAPS; ++n) sc[tid][n] = e[n]*rs;
            }
            __syncthreads();

            #pragma unroll
            for (int u = 0; u < 10; ++u) {
                int fl = tid + 256*u;          // 160 nt x 16 pd-quads
                int nt = fl >> 4, pdq = fl & 15;
                int n = nt >> 4, t = nt & 15;
                int p = p0 + (pdq >> 1), d0 = (pdq & 1)*4;
                float c = sc[pdq >> 1][n];
                float4 w = *(const float4*)&W[((p*NCAPS + n)*T + t)*D + d0];
                size_t base = (size_t)nt*PD + pd0 + pdq*4;
                *(__half2*)&g_Bq[base]     = __floats2half2_rn(w.x*c, w.y*c);
                *(__half2*)&g_Bq[base + 2] = __floats2half2_rn(w.z*c, w.w*c);
            }
        }
        gbar(5 + it*4);
    }
    // barriers used: 1 + (2,3,4,5) + (6,7,8,9) + (10) = 10 total (even),
    // so g_sense returns to 0 for the next launch / graph replay.
}

// ---------------- launch -----------------------------------------------------
extern "C" void kernel_launch(void* const* d_in, const int* in_sizes, int n_in,
                              void* d_out, int out_size) {
    (void)in_sizes; (void)n_in; (void)out_size;
    const float* x = (const float*)d_in[0];   // [512, 1152, 8]
    const float* W = (const float*)d_in[1];   // [1152, 10, 16, 8]
    float* out = (float*)d_out;               // [512, 10, 16, 1]

    cudaFuncSetAttribute((const void*)k_mega,
                         cudaFuncAttributeMaxDynamicSharedMemorySize, SMEM_BYTES);
    k_mega<<<NBLK, 256, SMEM_BYTES>>>(W, x, out);
}